// round 5
// baseline (speedup 1.0000x reference)
#include <cuda_runtime.h>
#include <cuda_bf16.h>
#include <stdint.h>
#include <float.h>

#define NROWS   65536
#define DIMS    256
#define NCODES  1024
#define TM      128        // rows per block
#define TC      64         // codes per chunk
#define NCHUNK  (NCODES / TC)
#define MARGIN  1e-2f      // >= 2 * deterministic bf16 distance-error bound (4e-3)
#define MAXC    20         // per-thread candidate cap (smem list)
#define ASTR    264        // padded bf16 row stride (528B; 528%128=16 -> ldmatrix conflict-free)

// ---- smem layout (bytes) -------------------------------------------------
#define OFF_A      0                         // 128 x ASTR bf16            67584
#define OFF_B0     67584                     // 64 x ASTR bf16             33792
#define OFF_B1     101376                    //                            33792
#define OFF_LIST   135168                    // u64[256][MAXC]             40960
#define OFF_E2     176128                    // f32[1024]                   4096
#define OFF_Z2     180224                    // f32[128]                     512
#define OFF_RMS    180736                    // f32[256][4]                 4096
#define OFF_FMIN   184832                    // i32[128]                     512
#define OFF_BEST   185344                    // u64[128]                    1024
#define OFF_IDX    186368                    // i32[128]                     512
#define OFF_ROVF   186880                    // i32[128]                     512
#define OFF_OVFL   187392                    // i32 count + i32[128]         520
#define OFF_RED    187912                    // double[256]                 2048
#define SMEM_BYTES (OFF_RED + 2048)

__device__ float  g_e2[NCODES];
__device__ double g_loss_accum;

// ---------------------------------------------------------------------------
__device__ __forceinline__ uint32_t smem_u32(const void* p) {
    uint32_t a;
    asm("{ .reg .u64 t; cvta.to.shared.u64 t, %1; cvt.u32.u64 %0, t; }"
        : "=r"(a) : "l"(p));
    return a;
}
__device__ __forceinline__ void ldm_x4(uint32_t* r, uint32_t a) {
    asm volatile("ldmatrix.sync.aligned.m8n8.x4.shared.b16 {%0,%1,%2,%3}, [%4];"
                 : "=r"(r[0]), "=r"(r[1]), "=r"(r[2]), "=r"(r[3]) : "r"(a));
}
__device__ __forceinline__ void mma_bf16(float* c, const uint32_t* a,
                                         const uint32_t* b) {
    asm volatile(
        "mma.sync.aligned.m16n8k16.row.col.f32.bf16.bf16.f32 "
        "{%0,%1,%2,%3},{%4,%5,%6,%7},{%8,%9},{%0,%1,%2,%3};"
        : "+f"(c[0]), "+f"(c[1]), "+f"(c[2]), "+f"(c[3])
        : "r"(a[0]), "r"(a[1]), "r"(a[2]), "r"(a[3]), "r"(b[0]), "r"(b[1]));
}

// ---------------------------------------------------------------------------
__global__ void vq_prep(const float* __restrict__ emb) {
    if (blockIdx.x == 0 && threadIdx.x == 0) g_loss_accum = 0.0;
    int warp = (blockIdx.x * blockDim.x + threadIdx.x) >> 5;
    int lane = threadIdx.x & 31;
    if (warp < NCODES) {
        const float* row = emb + warp * DIMS;
        float s = 0.f;
#pragma unroll
        for (int i = 0; i < DIMS / 32; i++) {
            float v = row[lane + 32 * i];
            s = __fadd_rn(s, __fmul_rn(v, v));
        }
#pragma unroll
        for (int o = 16; o > 0; o >>= 1)
            s = __fadd_rn(s, __shfl_down_sync(0xffffffffu, s, o));
        if (lane == 0) g_e2[warp] = s;
    }
}

// ---------------------------------------------------------------------------
// stage one 64x256 e-chunk (fp32 -> bf16), row-major padded, coalesced STS.64
__device__ __forceinline__ void stage_B(const float* __restrict__ eblk,
                                        char* bt, int tid) {
#pragma unroll 4
    for (int i = tid; i < TC * (DIMS / 4); i += 256) {
        int c  = i >> 6;
        int k4 = i & 63;
        float4 v = __ldg(&((const float4*)eblk)[(size_t)c * (DIMS / 4) + k4]);
        __nv_bfloat162 lo = __float22bfloat162_rn(make_float2(v.x, v.y));
        __nv_bfloat162 hi = __float22bfloat162_rn(make_float2(v.z, v.w));
        uint2 val = make_uint2(*(uint32_t*)&lo, *(uint32_t*)&hi);
        *(uint2*)(bt + ((size_t)c * ASTR + 4 * k4) * 2) = val;
    }
}

// exact fp32 distance in the R1-proven formula/rounding; packed for tiebreak
__device__ __forceinline__ unsigned long long exact_dist(
    const float* __restrict__ zrow, const float* __restrict__ emb,
    int code, float z2, const float* __restrict__ e2all) {
    const float4* zr = (const float4*)zrow;
    const float4* er = (const float4*)(emb + (size_t)code * DIMS);
    float d0 = 0.f, d1 = 0.f, d2 = 0.f, d3 = 0.f;
#pragma unroll 8
    for (int k4 = 0; k4 < DIMS / 4; k4++) {
        float4 zv = __ldg(&zr[k4]);
        float4 ev = __ldg(&er[k4]);
        d0 = fmaf(zv.x, ev.x, d0);
        d1 = fmaf(zv.y, ev.y, d1);
        d2 = fmaf(zv.z, ev.z, d2);
        d3 = fmaf(zv.w, ev.w, d3);
    }
    float dot  = __fadd_rn(__fadd_rn(d0, d1), __fadd_rn(d2, d3));
    float t    = __fadd_rn(z2, e2all[code]);
    float dist = __fsub_rn(t, __fmul_rn(2.0f, dot));
    return ((unsigned long long)__float_as_uint(dist) << 32) | (unsigned)code;
}

// ---------------------------------------------------------------------------
__global__ void __launch_bounds__(256, 1)
vq_main(const float* __restrict__ z, const float* __restrict__ emb,
        float* __restrict__ out) {
    extern __shared__ char sm[];
    char*   At    = sm + OFF_A;
    float*  e2all = (float*)(sm + OFF_E2);
    float*  z2sm  = (float*)(sm + OFF_Z2);
    float*  rmS   = (float*)(sm + OFF_RMS);
    int*    fminI = (int*)(sm + OFF_FMIN);
    unsigned long long* bestU = (unsigned long long*)(sm + OFF_BEST);
    int*    idxs  = (int*)(sm + OFF_IDX);
    int*    rowOvf= (int*)(sm + OFF_ROVF);
    int*    ovfl  = (int*)(sm + OFF_OVFL);      // [0]=count, [1..]=rows
    double* red   = (double*)(sm + OFF_RED);
    unsigned long long* lst =
        (unsigned long long*)(sm + OFF_LIST) + (size_t)threadIdx.x * MAXC;

    const int tid  = threadIdx.x;
    const int lane = tid & 31;
    const int warp = tid >> 5;
    const int wr   = warp >> 1;          // rows wr*32 .. +31
    const int wc   = warp & 1;           // cols wc*32 .. +31 within chunk
    const int rowBase = blockIdx.x * TM;
    const float* zblk = z + (size_t)rowBase * DIMS;
    const uint32_t smb = smem_u32(sm);

    // ---- init small state ----
    if (tid < TM) {
        fminI[tid]  = 0x7f800000;        // +inf
        bestU[tid]  = ~0ull;
        rowOvf[tid] = 0;
    }
    if (tid == 0) ovfl[0] = 0;

    // ---- stage A (z tile, fp32->bf16, padded row-major) ----
#pragma unroll 4
    for (int i = tid; i < TM * (DIMS / 4); i += 256) {
        int r  = i >> 6;
        int k4 = i & 63;
        float4 v = __ldg(&((const float4*)zblk)[(size_t)r * (DIMS / 4) + k4]);
        __nv_bfloat162 lo = __float22bfloat162_rn(make_float2(v.x, v.y));
        __nv_bfloat162 hi = __float22bfloat162_rn(make_float2(v.z, v.w));
        uint2 val = make_uint2(*(uint32_t*)&lo, *(uint32_t*)&hi);
        *(uint2*)(At + ((size_t)r * ASTR + 4 * k4) * 2) = val;
    }
    // e2 table
    for (int i = tid; i < NCODES; i += 256) e2all[i] = g_e2[i];
    // per-row exact ||z||^2 (R1 rounding order)
    if (tid < TM) {
        const float4* zr = (const float4*)(zblk + (size_t)tid * DIMS);
        float s = 0.f;
        for (int k4 = 0; k4 < DIMS / 4; k4++) {
            float4 v = __ldg(&zr[k4]);
            s = __fadd_rn(s, __fmul_rn(v.x, v.x));
            s = __fadd_rn(s, __fmul_rn(v.y, v.y));
            s = __fadd_rn(s, __fmul_rn(v.z, v.z));
            s = __fadd_rn(s, __fmul_rn(v.w, v.w));
        }
        z2sm[tid] = s;
    }
    stage_B(emb, sm + OFF_B0, tid);
    __syncthreads();

    // ---- per-lane ldmatrix base addresses ----
    const uint32_t aBase0 = smb + OFF_A +
        (uint32_t)((wr * 32 + (lane & 15)) * ASTR) * 2 + (lane >> 4) * 16;
    const uint32_t aBase1 = aBase0 + 16 * ASTR * 2;
    const int brow = (lane & 7) + ((lane & 16) >> 1);
    const uint32_t bOff0 =
        (uint32_t)((wc * 32 + brow) * ASTR) * 2 + ((lane >> 3) & 1) * 16;
    const uint32_t bOff1 = bOff0 + 16 * ASTR * 2;

    // rows owned by this thread's 4 slots
    const int g = lane >> 2;
    const int colb = (lane & 3) * 2;
    int rowOf[4];
#pragma unroll
    for (int s = 0; s < 4; s++) rowOf[s] = wr * 32 + s * 8 + g;
    float z2sl[4];
#pragma unroll
    for (int s = 0; s < 4; s++) z2sl[s] = z2sm[rowOf[s]];

    float rm0 = FLT_MAX, rm1 = FLT_MAX, rm2 = FLT_MAX, rm3 = FLT_MAX;
    int cn = 0;

    auto insert_cand = [&](float da, int tag) {
        if (cn == MAXC) {
            float* rs = rmS + tid * 4;
            rs[0] = rm0; rs[1] = rm1; rs[2] = rm2; rs[3] = rm3;
            int w = 0;
            for (int t = 0; t < MAXC; t++) {
                unsigned long long e = lst[t];
                float v = __uint_as_float((unsigned)(e >> 32));
                int s = ((int)(e & 0xFFFu)) >> 10;
                if (v <= rs[s] + MARGIN) lst[w++] = e;
            }
            cn = w;
        }
        if (cn < MAXC)
            lst[cn++] = ((unsigned long long)__float_as_uint(da) << 32) | (unsigned)tag;
        else
            rowOvf[rowOf[(tag >> 10) & 3]] = 1;
    };
#define TRACK(da, slot, rm, code)                                   \
    { float _d = (da);                                              \
      if (_d < rm) rm = _d;                                         \
      if (_d <= rm + MARGIN) insert_cand(_d, ((slot) << 10) | (code)); }

    // ================= chunk loop: bf16 HMMA + candidate tracking ==========
    for (int c = 0; c < NCHUNK; c++) {
        const int bb = c & 1;
        const uint32_t bbuf = smb + (bb ? OFF_B1 : OFF_B0);
        char* bnext = sm + ((bb ^ 1) ? OFF_B1 : OFF_B0);
        if (c + 1 < NCHUNK)
            stage_B(emb + (size_t)(c + 1) * TC * DIMS, bnext, tid);

        float acc[2][4][4];
#pragma unroll
        for (int m = 0; m < 2; m++)
#pragma unroll
            for (int n = 0; n < 4; n++)
#pragma unroll
                for (int e = 0; e < 4; e++) acc[m][n][e] = 0.f;

#pragma unroll
        for (int ks = 0; ks < 16; ks++) {
            const uint32_t ko = ks * 32;
            uint32_t A0[4], A1[4], B01[4], B23[4];
            ldm_x4(A0, aBase0 + ko);
            ldm_x4(A1, aBase1 + ko);
            ldm_x4(B01, bbuf + bOff0 + ko);
            ldm_x4(B23, bbuf + bOff1 + ko);
            mma_bf16(acc[0][0], A0, &B01[0]);
            mma_bf16(acc[0][1], A0, &B01[2]);
            mma_bf16(acc[0][2], A0, &B23[0]);
            mma_bf16(acc[0][3], A0, &B23[2]);
            mma_bf16(acc[1][0], A1, &B01[0]);
            mma_bf16(acc[1][1], A1, &B01[2]);
            mma_bf16(acc[1][2], A1, &B23[0]);
            mma_bf16(acc[1][3], A1, &B23[2]);
        }

        const int cBase = c * TC + wc * 32 + colb;
#pragma unroll
        for (int n = 0; n < 4; n++) {
            int cg = cBase + n * 8;
            float e20 = e2all[cg], e21 = e2all[cg + 1];
            TRACK(fmaf(-2.f, acc[0][n][0], z2sl[0] + e20), 0, rm0, cg);
            TRACK(fmaf(-2.f, acc[0][n][1], z2sl[0] + e21), 0, rm0, cg + 1);
            TRACK(fmaf(-2.f, acc[0][n][2], z2sl[1] + e20), 1, rm1, cg);
            TRACK(fmaf(-2.f, acc[0][n][3], z2sl[1] + e21), 1, rm1, cg + 1);
            TRACK(fmaf(-2.f, acc[1][n][0], z2sl[2] + e20), 2, rm2, cg);
            TRACK(fmaf(-2.f, acc[1][n][1], z2sl[2] + e21), 2, rm2, cg + 1);
            TRACK(fmaf(-2.f, acc[1][n][2], z2sl[3] + e20), 3, rm3, cg);
            TRACK(fmaf(-2.f, acc[1][n][3], z2sl[3] + e21), 3, rm3, cg + 1);
        }
        __syncthreads();
    }

    // ---- merge per-row approx minima ----
    atomicMin(&fminI[rowOf[0]], __float_as_int(rm0));
    atomicMin(&fminI[rowOf[1]], __float_as_int(rm1));
    atomicMin(&fminI[rowOf[2]], __float_as_int(rm2));
    atomicMin(&fminI[rowOf[3]], __float_as_int(rm3));
    __syncthreads();

    // ---- exact rescore of surviving candidates ----
    for (int t = 0; t < cn; t++) {
        unsigned long long e = lst[t];
        float v  = __uint_as_float((unsigned)(e >> 32));
        int tag  = (int)(e & 0xFFFu);
        int s    = tag >> 10;
        int code = tag & 1023;
        int row  = rowOf[s];
        if (v <= __int_as_float(fminI[row]) + MARGIN) {
            unsigned long long p =
                exact_dist(zblk + (size_t)row * DIMS, emb, code, z2sl[s], e2all);
            atomicMin(&bestU[row], p);
        }
    }
    __syncthreads();

    // ---- overflow rows: full exact scan (correct, ~never taken) ----
    if (tid < TM && rowOvf[tid]) {
        int p = atomicAdd(&ovfl[0], 1);
        ovfl[1 + p] = tid;
    }
    __syncthreads();
    int novf = ovfl[0];
    for (int f = 0; f < novf; f++) {
        int row = ovfl[1 + f];
        float z2r = z2sm[row];
        for (int code = tid; code < NCODES; code += 256) {
            unsigned long long p =
                exact_dist(zblk + (size_t)row * DIMS, emb, code, z2r, e2all);
            atomicMin(&bestU[row], p);
        }
    }
    if (novf) __syncthreads();

    if (tid < TM) idxs[tid] = (int)(bestU[tid] & 0xffffffffull);
    __syncthreads();

    // ================= epilogue: gather / STE / loss ======================
    double lsum = 0.0;
    float* outblk = out + (size_t)rowBase * DIMS;
    for (int i = tid; i < TM * (DIMS / 4); i += 256) {
        int r  = i >> 6;
        int k4 = i & 63;
        float4 zv = __ldg(&((const float4*)zblk)[(size_t)r * (DIMS / 4) + k4]);
        float4 qv = __ldg(&((const float4*)(emb + (size_t)idxs[r] * DIMS))[k4]);
        float4 ov; float d;
        d = __fsub_rn(qv.x, zv.x); ov.x = __fadd_rn(zv.x, d); lsum += (double)__fmul_rn(d, d);
        d = __fsub_rn(qv.y, zv.y); ov.y = __fadd_rn(zv.y, d); lsum += (double)__fmul_rn(d, d);
        d = __fsub_rn(qv.z, zv.z); ov.z = __fadd_rn(zv.z, d); lsum += (double)__fmul_rn(d, d);
        d = __fsub_rn(qv.w, zv.w); ov.w = __fadd_rn(zv.w, d); lsum += (double)__fmul_rn(d, d);
        ((float4*)outblk)[i] = ov;
    }
    red[tid] = lsum;
    __syncthreads();
    for (int s = 128; s > 0; s >>= 1) {
        if (tid < s) red[tid] += red[tid + s];
        __syncthreads();
    }
    if (tid == 0) atomicAdd(&g_loss_accum, red[0]);
}

// ---------------------------------------------------------------------------
__global__ void vq_finalize(float* __restrict__ out, int out_size) {
    double mean = g_loss_accum / (double)((size_t)NROWS * DIMS);
    float loss = (float)(0.5 * mean);
    out[out_size - 2] = loss;   // commitment_loss
    out[out_size - 1] = loss;   // emb_loss
}

// ---------------------------------------------------------------------------
extern "C" void kernel_launch(void* const* d_in, const int* in_sizes, int n_in,
                              void* d_out, int out_size) {
    const float* z   = (const float*)d_in[0];
    const float* emb = (const float*)d_in[1];
    if (n_in >= 2 && in_sizes[0] == NCODES * DIMS && in_sizes[1] == NROWS * DIMS) {
        emb = (const float*)d_in[0];
        z   = (const float*)d_in[1];
    }
    float* out = (float*)d_out;

    vq_prep<<<(NCODES * 32 + 255) / 256, 256>>>(emb);

    cudaFuncSetAttribute(vq_main, cudaFuncAttributeMaxDynamicSharedMemorySize,
                         SMEM_BYTES);
    vq_main<<<NROWS / TM, 256, SMEM_BYTES>>>(z, emb, out);

    vq_finalize<<<1, 1>>>(out, out_size);
}

// round 6
// speedup vs baseline: 18.9734x; 18.9734x over previous
#include <cuda_runtime.h>
#include <cuda_bf16.h>
#include <stdint.h>
#include <float.h>

#define NROWS   65536
#define DIMS    256
#define NCODES  1024
#define TM      128        // rows per block
#define TC      64         // codes per chunk
#define NCHUNK  (NCODES / TC)
#define MARGIN  2e-3f      // >= 2 * deterministic bf16 distance-error bound (8e-4)
#define MAXC    20         // per-thread candidate cap (smem list)
#define ASTR    264        // padded bf16 row stride (528B; conflict-free ldmatrix)

// ---- smem layout (bytes) -------------------------------------------------
#define OFF_A      0                         // 128 x ASTR bf16            67584
#define OFF_B0     67584                     // 64 x ASTR bf16             33792
#define OFF_B1     101376                    //                            33792
#define OFF_LIST   135168                    // u64[256][MAXC]             40960
#define OFF_E2     176128                    // f32[1024]                   4096
#define OFF_Z2     180224                    // f32[128]                     512
#define OFF_RMS    180736                    // f32[256][4]                 4096
#define OFF_FMIN   184832                    // i32[128]                     512
#define OFF_BEST   185344                    // u64[128]                    1024
#define OFF_IDX    186368                    // i32[128]                     512
#define OFF_ROVF   186880                    // i32[128]                     512
#define OFF_OVFL   187392                    // i32 count + i32[128]         520
#define OFF_RED    187912                    // double[256]                 2048
#define SMEM_BYTES (OFF_RED + 2048)

__device__ float  g_e2[NCODES];
__device__ double g_loss_accum;

// ---------------------------------------------------------------------------
__device__ __forceinline__ uint32_t smem_u32(const void* p) {
    uint32_t a;
    asm("{ .reg .u64 t; cvta.to.shared.u64 t, %1; cvt.u32.u64 %0, t; }"
        : "=r"(a) : "l"(p));
    return a;
}
__device__ __forceinline__ void ldm_x4(uint32_t* r, uint32_t a) {
    asm volatile("ldmatrix.sync.aligned.m8n8.x4.shared.b16 {%0,%1,%2,%3}, [%4];"
                 : "=r"(r[0]), "=r"(r[1]), "=r"(r[2]), "=r"(r[3]) : "r"(a));
}
__device__ __forceinline__ void mma_bf16(float* c, const uint32_t* a,
                                         const uint32_t* b) {
    asm volatile(
        "mma.sync.aligned.m16n8k16.row.col.f32.bf16.bf16.f32 "
        "{%0,%1,%2,%3},{%4,%5,%6,%7},{%8,%9},{%0,%1,%2,%3};"
        : "+f"(c[0]), "+f"(c[1]), "+f"(c[2]), "+f"(c[3])
        : "r"(a[0]), "r"(a[1]), "r"(a[2]), "r"(a[3]), "r"(b[0]), "r"(b[1]));
}

// ---------------------------------------------------------------------------
__global__ void vq_prep(const float* __restrict__ emb) {
    if (blockIdx.x == 0 && threadIdx.x == 0) g_loss_accum = 0.0;
    int warp = (blockIdx.x * blockDim.x + threadIdx.x) >> 5;
    int lane = threadIdx.x & 31;
    if (warp < NCODES) {
        const float* row = emb + warp * DIMS;
        float s = 0.f;
#pragma unroll
        for (int i = 0; i < DIMS / 32; i++) {
            float v = row[lane + 32 * i];
            s = __fadd_rn(s, __fmul_rn(v, v));
        }
#pragma unroll
        for (int o = 16; o > 0; o >>= 1)
            s = __fadd_rn(s, __shfl_down_sync(0xffffffffu, s, o));
        if (lane == 0) g_e2[warp] = s;
    }
}

// ---------------------------------------------------------------------------
// stage one 64x256 e-chunk (fp32 -> bf16), row-major padded, coalesced STS.64
__device__ __forceinline__ void stage_B(const float* __restrict__ eblk,
                                        char* bt, int tid) {
#pragma unroll 4
    for (int i = tid; i < TC * (DIMS / 4); i += 256) {
        int c  = i >> 6;
        int k4 = i & 63;
        float4 v = __ldg(&((const float4*)eblk)[(size_t)c * (DIMS / 4) + k4]);
        __nv_bfloat162 lo = __float22bfloat162_rn(make_float2(v.x, v.y));
        __nv_bfloat162 hi = __float22bfloat162_rn(make_float2(v.z, v.w));
        uint2 val = make_uint2(*(uint32_t*)&lo, *(uint32_t*)&hi);
        *(uint2*)(bt + ((size_t)c * ASTR + 4 * k4) * 2) = val;
    }
}

// exact fp32 distance in the R1-proven formula/rounding; packed for tiebreak
__device__ __forceinline__ unsigned long long exact_dist(
    const float* __restrict__ zrow, const float* __restrict__ emb,
    int code, float z2, const float* __restrict__ e2all) {
    const float4* zr = (const float4*)zrow;
    const float4* er = (const float4*)(emb + (size_t)code * DIMS);
    float d0 = 0.f, d1 = 0.f, d2 = 0.f, d3 = 0.f;
#pragma unroll 8
    for (int k4 = 0; k4 < DIMS / 4; k4++) {
        float4 zv = __ldg(&zr[k4]);
        float4 ev = __ldg(&er[k4]);
        d0 = fmaf(zv.x, ev.x, d0);
        d1 = fmaf(zv.y, ev.y, d1);
        d2 = fmaf(zv.z, ev.z, d2);
        d3 = fmaf(zv.w, ev.w, d3);
    }
    float dot  = __fadd_rn(__fadd_rn(d0, d1), __fadd_rn(d2, d3));
    float t    = __fadd_rn(z2, e2all[code]);
    float dist = __fsub_rn(t, __fmul_rn(2.0f, dot));
    return ((unsigned long long)__float_as_uint(dist) << 32) | (unsigned)code;
}

// ---------------------------------------------------------------------------
__global__ void __launch_bounds__(256, 1)
vq_main(const float* __restrict__ z, const float* __restrict__ emb,
        float* __restrict__ out) {
    extern __shared__ char sm[];
    char*   At    = sm + OFF_A;
    float*  e2all = (float*)(sm + OFF_E2);
    float*  z2sm  = (float*)(sm + OFF_Z2);
    float*  rmS   = (float*)(sm + OFF_RMS);
    int*    fminI = (int*)(sm + OFF_FMIN);
    unsigned long long* bestU = (unsigned long long*)(sm + OFF_BEST);
    int*    idxs  = (int*)(sm + OFF_IDX);
    int*    rowOvf= (int*)(sm + OFF_ROVF);
    int*    ovfl  = (int*)(sm + OFF_OVFL);      // [0]=count, [1..]=rows
    double* red   = (double*)(sm + OFF_RED);
    unsigned long long* lst =
        (unsigned long long*)(sm + OFF_LIST) + (size_t)threadIdx.x * MAXC;

    const int tid  = threadIdx.x;
    const int lane = tid & 31;
    const int warp = tid >> 5;
    const int wr   = warp >> 1;          // rows wr*32 .. +31
    const int wc   = warp & 1;           // cols wc*32 .. +31 within chunk
    const int rowBase = blockIdx.x * TM;
    const float* zblk = z + (size_t)rowBase * DIMS;
    const uint32_t smb = smem_u32(sm);

    // ---- init small state ----
    if (tid < TM) {
        fminI[tid]  = 0x7f800000;        // +inf
        bestU[tid]  = ~0ull;
        rowOvf[tid] = 0;
    }
    if (tid == 0) ovfl[0] = 0;

    // ---- stage A (z tile, fp32->bf16, padded row-major) ----
#pragma unroll 4
    for (int i = tid; i < TM * (DIMS / 4); i += 256) {
        int r  = i >> 6;
        int k4 = i & 63;
        float4 v = __ldg(&((const float4*)zblk)[(size_t)r * (DIMS / 4) + k4]);
        __nv_bfloat162 lo = __float22bfloat162_rn(make_float2(v.x, v.y));
        __nv_bfloat162 hi = __float22bfloat162_rn(make_float2(v.z, v.w));
        uint2 val = make_uint2(*(uint32_t*)&lo, *(uint32_t*)&hi);
        *(uint2*)(At + ((size_t)r * ASTR + 4 * k4) * 2) = val;
    }
    // e2 table
    for (int i = tid; i < NCODES; i += 256) e2all[i] = g_e2[i];
    // per-row exact ||z||^2 (R1 rounding order)
    if (tid < TM) {
        const float4* zr = (const float4*)(zblk + (size_t)tid * DIMS);
        float s = 0.f;
        for (int k4 = 0; k4 < DIMS / 4; k4++) {
            float4 v = __ldg(&zr[k4]);
            s = __fadd_rn(s, __fmul_rn(v.x, v.x));
            s = __fadd_rn(s, __fmul_rn(v.y, v.y));
            s = __fadd_rn(s, __fmul_rn(v.z, v.z));
            s = __fadd_rn(s, __fmul_rn(v.w, v.w));
        }
        z2sm[tid] = s;
    }
    stage_B(emb, sm + OFF_B0, tid);
    __syncthreads();

    // ---- per-lane ldmatrix base addresses ----
    const uint32_t aBase0 = smb + OFF_A +
        (uint32_t)((wr * 32 + (lane & 15)) * ASTR) * 2 + (lane >> 4) * 16;
    const uint32_t aBase1 = aBase0 + 16 * ASTR * 2;
    const int brow = (lane & 7) + ((lane & 16) >> 1);
    const uint32_t bOff0 =
        (uint32_t)((wc * 32 + brow) * ASTR) * 2 + ((lane >> 3) & 1) * 16;
    const uint32_t bOff1 = bOff0 + 16 * ASTR * 2;

    // rows owned by this thread's 4 slots
    const int g = lane >> 2;
    const int colb = (lane & 3) * 2;
    int rowOf[4];
#pragma unroll
    for (int s = 0; s < 4; s++) rowOf[s] = wr * 32 + s * 8 + g;
    float z2sl[4];
#pragma unroll
    for (int s = 0; s < 4; s++) z2sl[s] = z2sm[rowOf[s]];

    float rm0 = FLT_MAX, rm1 = FLT_MAX, rm2 = FLT_MAX, rm3 = FLT_MAX;
    int cn = 0;

    auto insert_cand = [&](float da, int tag) {
        if (cn == MAXC) {
            float* rs = rmS + tid * 4;
            rs[0] = rm0; rs[1] = rm1; rs[2] = rm2; rs[3] = rm3;
            int w = 0;
            for (int t = 0; t < MAXC; t++) {
                unsigned long long e = lst[t];
                float v = __uint_as_float((unsigned)(e >> 32));
                int s = ((int)(e & 0xFFFu)) >> 10;
                if (v <= rs[s] + MARGIN) lst[w++] = e;
            }
            cn = w;
        }
        if (cn < MAXC)
            lst[cn++] = ((unsigned long long)__float_as_uint(da) << 32) | (unsigned)tag;
        else
            rowOvf[rowOf[(tag >> 10) & 3]] = 1;
    };
#define TRACK(da, slot, rm, code)                                   \
    { float _d = (da);                                              \
      if (_d < rm) rm = _d;                                         \
      if (_d <= rm + MARGIN) insert_cand(_d, ((slot) << 10) | (code)); }

    // ================= chunk loop: bf16 HMMA + candidate tracking ==========
    for (int c = 0; c < NCHUNK; c++) {
        const int bb = c & 1;
        const uint32_t bbuf = smb + (bb ? OFF_B1 : OFF_B0);
        char* bnext = sm + ((bb ^ 1) ? OFF_B1 : OFF_B0);
        if (c + 1 < NCHUNK)
            stage_B(emb + (size_t)(c + 1) * TC * DIMS, bnext, tid);

        float acc[2][4][4];
#pragma unroll
        for (int m = 0; m < 2; m++)
#pragma unroll
            for (int n = 0; n < 4; n++)
#pragma unroll
                for (int e = 0; e < 4; e++) acc[m][n][e] = 0.f;

#pragma unroll
        for (int ks = 0; ks < 16; ks++) {
            const uint32_t ko = ks * 32;
            uint32_t A0[4], A1[4], B01[4], B23[4];
            ldm_x4(A0, aBase0 + ko);
            ldm_x4(A1, aBase1 + ko);
            ldm_x4(B01, bbuf + bOff0 + ko);
            ldm_x4(B23, bbuf + bOff1 + ko);
            mma_bf16(acc[0][0], A0, &B01[0]);
            mma_bf16(acc[0][1], A0, &B01[2]);
            mma_bf16(acc[0][2], A0, &B23[0]);
            mma_bf16(acc[0][3], A0, &B23[2]);
            mma_bf16(acc[1][0], A1, &B01[0]);
            mma_bf16(acc[1][1], A1, &B01[2]);
            mma_bf16(acc[1][2], A1, &B23[0]);
            mma_bf16(acc[1][3], A1, &B23[2]);
        }

        const int cBase = c * TC + wc * 32 + colb;
#pragma unroll
        for (int n = 0; n < 4; n++) {
            int cg = cBase + n * 8;
            float e20 = e2all[cg], e21 = e2all[cg + 1];
            TRACK(fmaf(-2.f, acc[0][n][0], z2sl[0] + e20), 0, rm0, cg);
            TRACK(fmaf(-2.f, acc[0][n][1], z2sl[0] + e21), 0, rm0, cg + 1);
            TRACK(fmaf(-2.f, acc[0][n][2], z2sl[1] + e20), 1, rm1, cg);
            TRACK(fmaf(-2.f, acc[0][n][3], z2sl[1] + e21), 1, rm1, cg + 1);
            TRACK(fmaf(-2.f, acc[1][n][0], z2sl[2] + e20), 2, rm2, cg);
            TRACK(fmaf(-2.f, acc[1][n][1], z2sl[2] + e21), 2, rm2, cg + 1);
            TRACK(fmaf(-2.f, acc[1][n][2], z2sl[3] + e20), 3, rm3, cg);
            TRACK(fmaf(-2.f, acc[1][n][3], z2sl[3] + e21), 3, rm3, cg + 1);
        }
        __syncthreads();
    }

    // ---- merge per-row approx minima ----
    atomicMin(&fminI[rowOf[0]], __float_as_int(rm0));
    atomicMin(&fminI[rowOf[1]], __float_as_int(rm1));
    atomicMin(&fminI[rowOf[2]], __float_as_int(rm2));
    atomicMin(&fminI[rowOf[3]], __float_as_int(rm3));
    __syncthreads();

    // ---- exact rescore of surviving candidates ----
    for (int t = 0; t < cn; t++) {
        unsigned long long e = lst[t];
        float v  = __uint_as_float((unsigned)(e >> 32));
        int tag  = (int)(e & 0xFFFu);
        int s    = tag >> 10;
        int code = tag & 1023;
        int row  = rowOf[s];
        if (v <= __int_as_float(fminI[row]) + MARGIN) {
            unsigned long long p =
                exact_dist(zblk + (size_t)row * DIMS, emb, code, z2sl[s], e2all);
            atomicMin(&bestU[row], p);
        }
    }
    __syncthreads();

    // ---- overflow rows: full exact scan (correct, ~never taken) ----
    if (tid < TM && rowOvf[tid]) {
        int p = atomicAdd(&ovfl[0], 1);
        ovfl[1 + p] = tid;
    }
    __syncthreads();
    int novf = ovfl[0];
    for (int f = 0; f < novf; f++) {
        int row = ovfl[1 + f];
        float z2r = z2sm[row];
        for (int code = tid; code < NCODES; code += 256) {
            unsigned long long p =
                exact_dist(zblk + (size_t)row * DIMS, emb, code, z2r, e2all);
            atomicMin(&bestU[row], p);
        }
    }
    if (novf) __syncthreads();

    if (tid < TM) idxs[tid] = (int)(bestU[tid] & 0xffffffffull);
    __syncthreads();

    // ================= epilogue: gather / STE / loss ======================
    double lsum = 0.0;
    float* outblk = out + (size_t)rowBase * DIMS;
    for (int i = tid; i < TM * (DIMS / 4); i += 256) {
        int r  = i >> 6;
        int k4 = i & 63;
        float4 zv = __ldg(&((const float4*)zblk)[(size_t)r * (DIMS / 4) + k4]);
        float4 qv = __ldg(&((const float4*)(emb + (size_t)idxs[r] * DIMS))[k4]);
        float4 ov; float d;
        d = __fsub_rn(qv.x, zv.x); ov.x = __fadd_rn(zv.x, d); lsum += (double)__fmul_rn(d, d);
        d = __fsub_rn(qv.y, zv.y); ov.y = __fadd_rn(zv.y, d); lsum += (double)__fmul_rn(d, d);
        d = __fsub_rn(qv.z, zv.z); ov.z = __fadd_rn(zv.z, d); lsum += (double)__fmul_rn(d, d);
        d = __fsub_rn(qv.w, zv.w); ov.w = __fadd_rn(zv.w, d); lsum += (double)__fmul_rn(d, d);
        ((float4*)outblk)[i] = ov;
    }
    red[tid] = lsum;
    __syncthreads();
    for (int s = 128; s > 0; s >>= 1) {
        if (tid < s) red[tid] += red[tid + s];
        __syncthreads();
    }
    if (tid == 0) atomicAdd(&g_loss_accum, red[0]);
}

// ---------------------------------------------------------------------------
__global__ void vq_finalize(float* __restrict__ out, int out_size) {
    double mean = g_loss_accum / (double)((size_t)NROWS * DIMS);
    float loss = (float)(0.5 * mean);
    out[out_size - 2] = loss;   // commitment_loss
    out[out_size - 1] = loss;   // emb_loss
}

// ---------------------------------------------------------------------------
extern "C" void kernel_launch(void* const* d_in, const int* in_sizes, int n_in,
                              void* d_out, int out_size) {
    const float* z   = (const float*)d_in[0];
    const float* emb = (const float*)d_in[1];
    if (n_in >= 2 && in_sizes[0] == NCODES * DIMS && in_sizes[1] == NROWS * DIMS) {
        emb = (const float*)d_in[0];
        z   = (const float*)d_in[1];
    }
    float* out = (float*)d_out;

    vq_prep<<<(NCODES * 32 + 255) / 256, 256>>>(emb);

    cudaFuncSetAttribute(vq_main, cudaFuncAttributeMaxDynamicSharedMemorySize,
                         SMEM_BYTES);
    vq_main<<<NROWS / TM, 256, SMEM_BYTES>>>(z, emb, out);

    vq_finalize<<<1, 1>>>(out, out_size);
}